// round 15
// baseline (speedup 1.0000x reference)
#include <cuda_runtime.h>
#include <cuda_bf16.h>
#include <cuda_fp16.h>
#include <stdint.h>
#include <math.h>

#define BS   128
#define SEQ  128
#define CCH  6
#define LL   20
#define NROWS (BS*SEQ)      // 16384
#define DD   64
#define HH   256
#define MAL  10
#define WTOT 1280           // MAL*SEQ
#define KSEL 3276           // int(16384*0.2)
#define AMAX 18432

// ---------------- scratch (device globals; no runtime alloc allowed) ----------
__device__ float    g_bridge[NROWS*DD];          // 4 MB
__device__ float    g_loss[NROWS];               // natural order [b][t]
__device__ unsigned g_scores[NROWS];             // float bits
__device__ int      g_desc[AMAX*3];              // (b, start, end) per atom
__device__ int      g_total;
__device__ unsigned g_hd16[(size_t)AMAX*128];    // hd packed fp16x2
__device__ unsigned g_B16[128*7680];             // ad2w packed fp16x2, [kp][n]

// --------- fp16 pack helper ---------
__device__ __forceinline__ unsigned pk16(float v0, float v1)
{
    __half h0 = __float2half(v0);
    __half h1 = __float2half(v1);
    return (unsigned)__half_as_ushort(h0) | ((unsigned)__half_as_ushort(h1) << 16);
}
__device__ __forceinline__ void mma16816h(float* c, const unsigned* a, unsigned b0, unsigned b1)
{
    asm volatile(
        "mma.sync.aligned.m16n8k16.row.col.f32.f16.f16.f32 "
        "{%0,%1,%2,%3}, {%4,%5,%6,%7}, {%8,%9}, {%0,%1,%2,%3};\n"
        : "+f"(c[0]), "+f"(c[1]), "+f"(c[2]), "+f"(c[3])
        : "r"(a[0]), "r"(a[1]), "r"(a[2]), "r"(a[3]), "r"(b0), "r"(b1));
}

// =========================== K1: CNN encoder + bridge ========================
__global__ __launch_bounds__(256) void k_encoder(
    const float* __restrict__ x,
    const float* __restrict__ c1w, const float* __restrict__ c1b,
    const float* __restrict__ c2w, const float* __restrict__ c2b,
    const float* __restrict__ c3w, const float* __restrict__ c3b,
    const float* __restrict__ brw, const float* __restrict__ brb,
    float* __restrict__ o_bresh, float* __restrict__ o_fin)
{
    __shared__ float s_c1w[288], s_c1b[16], s_c2w[1536], s_c2b[32];
    __shared__ float s_c3w[3072], s_c3b[32], s_brb[64];
    __shared__ float bufA[8][320], bufB[8][320];
    int tid = threadIdx.x;
    for (int i = tid; i < 288;  i += 256) s_c1w[i] = c1w[i];
    for (int i = tid; i < 16;   i += 256) s_c1b[i] = c1b[i];
    for (int i = tid; i < 1536; i += 256) s_c2w[i] = c2w[i];
    for (int i = tid; i < 32;   i += 256) s_c2b[i] = c2b[i];
    for (int i = tid; i < 3072; i += 256) s_c3w[i] = c3w[i];
    for (int i = tid; i < 32;   i += 256) s_c3b[i] = c3b[i];
    for (int i = tid; i < 64;   i += 256) s_brb[i] = brb[i];
    __syncthreads();

    int w = tid >> 5, l = tid & 31;
    int n = blockIdx.x * 8 + w;
    float* A_ = bufA[w];
    float* B_ = bufB[w];

    for (int i = l; i < 120; i += 32) A_[i] = x[(size_t)n*120 + i];
    __syncwarp();

    {
        int oc = l >> 1, half = l & 1;
        int base0 = half * 10;
        float acc[10];
        float b = s_c1b[oc];
        #pragma unroll
        for (int j = 0; j < 10; j++) acc[j] = b;
        #pragma unroll
        for (int ic = 0; ic < 6; ic++) {
            const float* wv = &s_c1w[(oc*6 + ic)*3];
            float w0 = wv[0], w1 = wv[1], w2 = wv[2];
            const float* xr = &A_[ic*20 + base0];
            float xv[12];
            xv[0] = (half == 0) ? 0.f : xr[-1];
            #pragma unroll
            for (int j = 1; j < 11; j++) xv[j] = xr[j-1];
            xv[11] = (half == 1) ? 0.f : xr[10];
            #pragma unroll
            for (int j = 0; j < 10; j++) {
                acc[j] += w0*xv[j];
                acc[j] += w1*xv[j+1];
                acc[j] += w2*xv[j+2];
            }
        }
        #pragma unroll
        for (int j = 0; j < 5; j++)
            B_[oc*10 + half*5 + j] = fmaxf(fmaxf(acc[2*j], acc[2*j+1]), 0.f);
    }
    __syncwarp();

    {
        float acc[10];
        float b = s_c2b[l];
        #pragma unroll
        for (int j = 0; j < 10; j++) acc[j] = b;
        #pragma unroll
        for (int ic = 0; ic < 16; ic++) {
            const float* wv = &s_c2w[(l*16 + ic)*3];
            float w0 = wv[0], w1 = wv[1], w2 = wv[2];
            const float* xr = &B_[ic*10];
            float xv[12];
            xv[0] = 0.f;
            #pragma unroll
            for (int j = 1; j < 11; j++) xv[j] = xr[j-1];
            xv[11] = 0.f;
            #pragma unroll
            for (int j = 0; j < 10; j++) {
                acc[j] += w0*xv[j];
                acc[j] += w1*xv[j+1];
                acc[j] += w2*xv[j+2];
            }
        }
        __syncwarp();
        #pragma unroll
        for (int j = 0; j < 5; j++)
            A_[l*5 + j] = fmaxf(fmaxf(acc[2*j], acc[2*j+1]), 0.f);
    }
    __syncwarp();

    {
        float acc[5];
        float b = s_c3b[l];
        #pragma unroll
        for (int j = 0; j < 5; j++) acc[j] = b;
        #pragma unroll
        for (int ic = 0; ic < 32; ic++) {
            const float* wv = &s_c3w[(l*32 + ic)*3];
            float w0 = wv[0], w1 = wv[1], w2 = wv[2];
            const float* xr = &A_[ic*5];
            float xv[7];
            xv[0] = 0.f;
            #pragma unroll
            for (int j = 1; j < 6; j++) xv[j] = xr[j-1];
            xv[6] = 0.f;
            #pragma unroll
            for (int j = 0; j < 5; j++) {
                acc[j] += w0*xv[j];
                acc[j] += w1*xv[j+1];
                acc[j] += w2*xv[j+2];
            }
        }
        __syncwarp();
        B_[l*2 + 0] = fmaxf(fmaxf(acc[0], acc[1]), 0.f);
        B_[l*2 + 1] = fmaxf(fmaxf(acc[2], acc[3]), 0.f);
    }
    __syncwarp();

    #pragma unroll
    for (int cc = 0; cc < 2; cc++) {
        int c = l + cc*32;
        float v = s_brb[c];
        #pragma unroll 8
        for (int i2 = 0; i2 < 64; i2++) v += B_[i2] * __ldg(&brw[i2*64 + c]);
        v = 1.f / (1.f + expf(-v));
        g_bridge[(size_t)n*64 + c] = v;
        o_bresh [(size_t)n*64 + c] = v;
        o_fin   [(size_t)n*64 + c] = v;
    }
}

// ============================ K2: forecast MLP + loss ========================
__global__ __launch_bounds__(256) void k_forecast(
    const float* __restrict__ f1w, const float* __restrict__ f1b,
    const float* __restrict__ f2w, const float* __restrict__ f2b,
    const float* __restrict__ imu_mask,
    float* __restrict__ o_fo, float* __restrict__ o_fm, float* __restrict__ o_loss)
{
    __shared__ __align__(16) float shft[16*64];
    __shared__ __align__(16) float feat[16*256];
    __shared__ float fo[16*64];
    __shared__ float rmask[16];
    int tid = threadIdx.x;
    int n0 = blockIdx.x * 16;

    for (int i = tid; i < 256; i += 256) {
        int r = i >> 4, c4 = i & 15;
        int n = n0 + r, t = n & 127;
        float4 v = make_float4(0.f, 0.f, 0.f, 0.f);
        if (t != 0) v = *(const float4*)&g_bridge[((size_t)n - 1)*64 + c4*4];
        *(float4*)&shft[r*64 + c4*4] = v;
    }
    if (tid < 16) {
        int n = n0 + tid, t = n & 127;
        rmask[tid] = (t == 0) ? 0.f : imu_mask[(size_t)n*120];
    }
    __syncthreads();

    {
        float acc[16];
        float b = f1b[tid];
        #pragma unroll
        for (int r = 0; r < 16; r++) acc[r] = b;
        for (int c4 = 0; c4 < 16; c4++) {
            float w0 = f1w[(c4*4    )*256 + tid];
            float w1 = f1w[(c4*4 + 1)*256 + tid];
            float w2 = f1w[(c4*4 + 2)*256 + tid];
            float w3 = f1w[(c4*4 + 3)*256 + tid];
            #pragma unroll
            for (int r = 0; r < 16; r++) {
                float4 s = *(const float4*)&shft[r*64 + c4*4];
                acc[r] += s.x * w0;
                acc[r] += s.y * w1;
                acc[r] += s.z * w2;
                acc[r] += s.w * w3;
            }
        }
        #pragma unroll
        for (int r = 0; r < 16; r++) feat[r*256 + tid] = fmaxf(acc[r], 0.f);
    }
    __syncthreads();

    {
        int col = tid & 63, rg = tid >> 6;
        float acc[4];
        float b = f2b[col];
        #pragma unroll
        for (int u = 0; u < 4; u++) acc[u] = b;
        for (int i4 = 0; i4 < 64; i4++) {
            float w0 = f2w[(i4*4    )*64 + col];
            float w1 = f2w[(i4*4 + 1)*64 + col];
            float w2 = f2w[(i4*4 + 2)*64 + col];
            float w3 = f2w[(i4*4 + 3)*64 + col];
            #pragma unroll
            for (int u = 0; u < 4; u++) {
                float4 fv = *(const float4*)&feat[(rg*4+u)*256 + i4*4];
                acc[u] += fv.x * w0;
                acc[u] += fv.y * w1;
                acc[u] += fv.z * w2;
                acc[u] += fv.w * w3;
            }
        }
        #pragma unroll
        for (int u = 0; u < 4; u++) {
            int r = rg*4 + u;
            fo[r*64 + col] = acc[u];
            o_fo[((size_t)(n0 + r))*64 + col] = acc[u];
            o_fm[((size_t)(n0 + r))*64 + col] = rmask[r];
        }
    }
    __syncthreads();

    if (tid < 16) {
        int n = n0 + tid;
        float m = rmask[tid];
        float s = 0.f;
        for (int d = 0; d < 64; d++) {
            float df = (fo[tid*64 + d] - g_bridge[(size_t)n*64 + d]) * m;
            s += df * df;
        }
        float loss = s / 64.f;
        o_loss[n] = loss;
        g_loss[n] = loss;
        g_scores[n] = __float_as_uint(loss * m);
    }
}

// ======= K3: fused exact k-th largest (radix select) + segment build =========
// warp-shuffle scans: ~19 block barriers total (was 66).
__global__ __launch_bounds__(1024) void k_selectseg()
{
    __shared__ unsigned hist[256];
    __shared__ unsigned wtot[8];
    __shared__ unsigned sprefix;
    __shared__ int srem;
    __shared__ unsigned flagw[128][4];
    __shared__ int wpre[4];
    __shared__ int sc_s[128];
    int tid = threadIdx.x;
    int w8 = tid >> 5, l = tid & 31;

    unsigned v[16];
    float lv[16];
    #pragma unroll
    for (int j = 0; j < 16; j++) {
        v[j]  = g_scores[tid + j*1024];
        lv[j] = g_loss[tid + j*1024];
    }

    if (tid == 0) { sprefix = 0u; srem = KSEL; }
    __syncthreads();
    for (int pass = 0; pass < 4; pass++) {
        int shift = 24 - pass * 8;
        if (tid < 256) hist[tid] = 0;
        __syncthreads();
        unsigned pref = sprefix;
        int rem = srem;
        unsigned mask = (pass == 0) ? 0u : (0xFFFFFFFFu << (shift + 8));
        #pragma unroll
        for (int j = 0; j < 16; j++)
            if ((v[j] & mask) == pref) atomicAdd(&hist[(v[j] >> shift) & 255], 1u);
        __syncthreads();
        // suffix scan via warp shuffles (warps 0..7 own 32 bins each)
        unsigned hval = 0, sval = 0;
        if (tid < 256) hval = hist[tid];
        sval = hval;
        #pragma unroll
        for (int d = 1; d < 32; d <<= 1) {
            unsigned o = __shfl_down_sync(0xFFFFFFFFu, sval, d);
            if (l + d < 32) sval += o;
        }
        if (tid < 256 && l == 0) wtot[w8] = sval;   // warp-block suffix total
        __syncthreads();
        if (tid < 256) {
            unsigned add = 0;
            #pragma unroll
            for (int ww = 1; ww < 8; ww++)
                if (w8 + ww < 8) add += wtot[w8 + ww];
            unsigned sfxv = sval + add;              // sum of bins >= tid
            unsigned above = sfxv - hval;            // sum of bins >  tid
            if (sfxv >= (unsigned)rem && above < (unsigned)rem) {
                sprefix = pref | ((unsigned)tid << shift);
                srem = rem - (int)above;
            }
        }
        __syncthreads();
    }
    float cutoff = __uint_as_float(sprefix);

    #pragma unroll
    for (int k = 0; k < 16; k++) {
        int i = tid + k*1024;
        bool f = lv[k] > cutoff;
        unsigned bal = __ballot_sync(0xFFFFFFFFu, f);
        if ((tid & 31) == 0) flagw[i >> 7][(i & 127) >> 5] = bal;
    }
    __syncthreads();

    int segs[160];
    int ns = 0;
    if (tid < 128) {
        int prev = -1;
        #pragma unroll
        for (int wi = 0; wi < 4; wi++) {
            unsigned wv = flagw[tid][wi];
            while (wv) {
                int t = wi*32 + __ffs(wv) - 1;
                wv &= wv - 1;
                if (prev >= 0) {
                    if (t - prev > MAL) {
                        segs[ns++] = prev;
                        int cur = prev;
                        while (cur < t) { cur += MAL; if (cur >= t) break; segs[ns++] = cur; }
                    } else {
                        segs[ns++] = prev;
                    }
                }
                prev = t;
            }
        }
        if (prev >= 0) segs[ns++] = prev;
    }
    // inclusive prefix scan of ns over threads 0..127 (4 warps) via shuffles
    int pval = ns;
    if (tid < 128) {
        #pragma unroll
        for (int d = 1; d < 32; d <<= 1) {
            int o = __shfl_up_sync(0xFFFFFFFFu, pval, d);
            if (l >= d) pval += o;
        }
        if (l == 31) wpre[w8] = pval;
    }
    __syncthreads();
    if (tid < 128) {
        int add = 0;
        #pragma unroll
        for (int ww = 0; ww < 4; ww++)
            if (ww < w8) add += wpre[ww];
        int inc = pval + add;                        // inclusive prefix
        sc_s[tid] = inc;
        int off = inc - ns;
        if (tid == 127) {
            int tot = inc;
            g_total = tot;
            if (tot == 0) { g_desc[0] = -1; g_desc[1] = 0; g_desc[2] = 0; }
        }
        int last = 0;
        for (int i = 0; i < ns; i++) {
            int e = segs[i];
            g_desc[(off + i)*3 + 0] = tid;
            g_desc[(off + i)*3 + 1] = last;
            g_desc[(off + i)*3 + 2] = e;
            last = e;
        }
    }
}

// ===== K5: fused atom fill (mask/atoms) + atom encoder -> hd fp16 packed =====
__global__ __launch_bounds__(256) void k_atomenc(
    const float* __restrict__ x,
    float4* __restrict__ o_mask, float4* __restrict__ o_atoms,
    const float* __restrict__ ae1w, const float* __restrict__ ae1b,
    const float* __restrict__ ae2w, const float* __restrict__ ae2b,
    const float* __restrict__ ae3w, const float* __restrict__ ae3b,
    const float* __restrict__ ad1w, const float* __restrict__ ad1b)
{
    __shared__ float saf[640], sw1[6144];
    __shared__ float spart[8][320];
    __shared__ float sh1[320], sp1[160], sh2[80], semb[32];
    int g = blockIdx.x, tid = threadIdx.x;
    int w = tid >> 5, l = tid & 31;
    int b = g_desc[g*3 + 0], s = g_desc[g*3 + 1], e = g_desc[g*3 + 2];

    for (int i = tid; i < 6144; i += 256) sw1[i] = ae1w[i];
    for (int i = tid; i < 640; i += 256) {
        int d = i / 10, t = i % 10;
        int row = e - 10 + t;
        saf[i] = (b >= 0 && row >= s) ? g_bridge[((size_t)b*SEQ + row)*64 + d] : 0.f;
    }

    {
        const float4 z4 = make_float4(0.f, 0.f, 0.f, 0.f);
        const float4 o4 = make_float4(1.f, 1.f, 1.f, 1.f);
        int wdt = e - s, ap = WTOT - wdt * LL;
        for (int i = tid; i < 1920; i += 256) {
            float4 mv = z4, val = z4;
            if (b >= 0) {
                int c = i / 320;
                int r4 = i - c*320;
                int colg = r4*4 - ap;
                if (colg >= 0) {
                    mv = o4;
                    int trow = colg / 20;
                    int ll = colg - trow*20;
                    val = *(const float4*)&x[(((size_t)b*SEQ + s + trow)*CCH + c)*LL + ll];
                }
            }
            o_mask [(size_t)g*1920 + i] = mv;
            o_atoms[(size_t)g*1920 + i] = val;
        }
    }
    __syncthreads();

    {
        float acc[10];
        #pragma unroll
        for (int j = 0; j < 10; j++) acc[j] = 0.f;
        #pragma unroll
        for (int ick = 0; ick < 8; ick++) {
            int ic = w*8 + ick;
            const float* wv = &sw1[(l*64 + ic)*3];
            float w0 = wv[0], w1 = wv[1], w2 = wv[2];
            float xv[12];
            xv[0] = 0.f;
            #pragma unroll
            for (int j = 1; j < 11; j++) xv[j] = saf[ic*10 + j - 1];
            xv[11] = 0.f;
            #pragma unroll
            for (int j = 0; j < 10; j++) {
                acc[j] += w0*xv[j];
                acc[j] += w1*xv[j+1];
                acc[j] += w2*xv[j+2];
            }
        }
        #pragma unroll
        for (int j = 0; j < 10; j++) spart[w][l*10 + j] = acc[j];
    }
    __syncthreads();
    for (int i = tid; i < 320; i += 256) {
        float sv = ae1b[i/10];
        #pragma unroll
        for (int ww = 0; ww < 8; ww++) sv += spart[ww][i];
        sh1[i] = fmaxf(sv, 0.f);
    }
    __syncthreads();
    for (int i = tid; i < 160; i += 256) { int oc=i/5, p=i%5; sp1[i] = fmaxf(sh1[oc*10+2*p], sh1[oc*10+2*p+1]); }
    __syncthreads();
    for (int i = tid; i < 80; i += 256) {
        int oc = i / 5, p = i % 5;
        float v = ae2b[oc];
        #pragma unroll
        for (int ic = 0; ic < 32; ic++) {
            const float* wv = &ae2w[(oc*32+ic)*3];
            const float* xr = &sp1[ic*5];
            if (p > 0) v += wv[0]*xr[p-1];
            v += wv[1]*xr[p];
            if (p < 4) v += wv[2]*xr[p+1];
        }
        sh2[i] = fmaxf(v, 0.f);
    }
    __syncthreads();
    for (int i = tid; i < 32; i += 256) {
        float v = ae3b[i];
        for (int j = 0; j < 80; j++) v += sh2[j] * ae3w[j*32 + i];
        semb[i] = v;
    }
    __syncthreads();
    if (tid < 128) {
        int c0 = 2*tid;
        float v0 = ad1b[c0], v1 = ad1b[c0 + 1];
        #pragma unroll
        for (int j = 0; j < 32; j++) {
            float ev = semb[j];
            v0 += ev * ad1w[j*256 + c0];
            v1 += ev * ad1w[j*256 + c0 + 1];
        }
        v0 = fmaxf(v0, 0.f);
        v1 = fmaxf(v1, 0.f);
        g_hd16[(size_t)g*128 + tid] = pk16(v0, v1);
    }
}

// ============ K6p: pre-pack ad2w into fp16x2  ================================
__global__ __launch_bounds__(256) void k_prepB(const float* __restrict__ Bw)
{
    int i = blockIdx.x * 256 + threadIdx.x;
    int kp = i / 1920;
    int n0 = (i - kp*1920) * 4;
    const float4 a = *(const float4*)&Bw[(size_t)(2*kp)*7680 + n0];
    const float4 b = *(const float4*)&Bw[(size_t)(2*kp + 1)*7680 + n0];
    uint4 H;
    H.x = pk16(a.x, b.x);
    H.y = pk16(a.y, b.y);
    H.z = pk16(a.z, b.z);
    H.w = pk16(a.w, b.w);
    *(uint4*)&g_B16[(size_t)kp*7680 + n0] = H;
}

// ==== K6b: atom_gen GEMM via fp16 tensor cores (software-pipelined k-loop) ===
#define ASTR 136
__global__ __launch_bounds__(256) void k_gemm_atomgen(
    const float* __restrict__ bias, float* __restrict__ Cout, int M)
{
    __shared__ __align__(16) unsigned As[16][ASTR];
    __shared__ __align__(16) unsigned Bs[16][ASTR];
    int tid = threadIdx.x;
    int lane = tid & 31, wid = tid >> 5;
    int warp_m = wid & 3, warp_n = wid >> 2;
    int gtop = lane >> 2, tig = lane & 3;
    int row0 = blockIdx.y * 128, col0 = blockIdx.x * 128;

    float acc[2][8][4];
    #pragma unroll
    for (int r = 0; r < 2; r++)
        #pragma unroll
        for (int nt = 0; nt < 8; nt++)
            #pragma unroll
            for (int q = 0; q < 4; q++) acc[r][nt][q] = 0.f;

    unsigned aR[8];
    uint4 bR[2];

    {
        int kp2 = 0;
        #pragma unroll
        for (int it = 0; it < 8; it++) {
            int idx = tid + it*256;
            int m = idx >> 4, kp = idx & 15;
            int gr = row0 + m;
            aR[it] = (gr < M) ? g_hd16[(size_t)gr*128 + kp2 + kp] : 0u;
        }
        #pragma unroll
        for (int it = 0; it < 2; it++) {
            int e = tid + it*256;
            int kp = e >> 5, n4 = (e & 31) << 2;
            bR[it] = *(const uint4*)&g_B16[(size_t)(kp2 + kp)*7680 + col0 + n4];
        }
    }

    for (int chunk = 0; chunk < 8; chunk++) {
        #pragma unroll
        for (int it = 0; it < 8; it++) {
            int idx = tid + it*256;
            int m = idx >> 4, kp = idx & 15;
            As[kp][m] = aR[it];
        }
        #pragma unroll
        for (int it = 0; it < 2; it++) {
            int e = tid + it*256;
            int kp = e >> 5, n4 = (e & 31) << 2;
            *(uint4*)&Bs[kp][n4] = bR[it];
        }
        __syncthreads();

        if (chunk < 7) {
            int kp2 = (chunk + 1) * 16;
            #pragma unroll
            for (int it = 0; it < 8; it++) {
                int idx = tid + it*256;
                int m = idx >> 4, kp = idx & 15;
                int gr = row0 + m;
                aR[it] = (gr < M) ? g_hd16[(size_t)gr*128 + kp2 + kp] : 0u;
            }
            #pragma unroll
            for (int it = 0; it < 2; it++) {
                int e = tid + it*256;
                int kp = e >> 5, n4 = (e & 31) << 2;
                bR[it] = *(const uint4*)&g_B16[(size_t)(kp2 + kp)*7680 + col0 + n4];
            }
        }

        #pragma unroll
        for (int ks = 0; ks < 2; ks++) {
            unsigned a[2][4];
            #pragma unroll
            for (int r = 0; r < 2; r++) {
                int mrow = warp_m*32 + r*16;
                a[r][0] = As[ks*8 + tig    ][mrow + gtop];
                a[r][1] = As[ks*8 + tig    ][mrow + gtop + 8];
                a[r][2] = As[ks*8 + tig + 4][mrow + gtop];
                a[r][3] = As[ks*8 + tig + 4][mrow + gtop + 8];
            }
            #pragma unroll
            for (int nt = 0; nt < 8; nt++) {
                int ncol = warp_n*64 + nt*8 + gtop;
                unsigned b0 = Bs[ks*8 + tig    ][ncol];
                unsigned b1 = Bs[ks*8 + tig + 4][ncol];
                #pragma unroll
                for (int r = 0; r < 2; r++)
                    mma16816h(acc[r][nt], a[r], b0, b1);
            }
        }
        __syncthreads();
    }

    #pragma unroll
    for (int r = 0; r < 2; r++) {
        int gr0 = row0 + warp_m*32 + r*16 + gtop;
        #pragma unroll
        for (int nt = 0; nt < 8; nt++) {
            int gc = col0 + warp_n*64 + nt*8 + 2*tig;
            float b0 = bias[gc], b1 = bias[gc + 1];
            if (gr0 < M) {
                float2 v = make_float2(acc[r][nt][0] + b0, acc[r][nt][1] + b1);
                *(float2*)&Cout[(size_t)gr0*7680 + gc] = v;
            }
            if (gr0 + 8 < M) {
                float2 v = make_float2(acc[r][nt][2] + b0, acc[r][nt][3] + b1);
                *(float2*)&Cout[(size_t)(gr0 + 8)*7680 + gc] = v;
            }
        }
    }
}

// ============================ K7: decoder -> imu_gen =========================
__global__ __launch_bounds__(256) void k_decoder(
    const float* __restrict__ d1w, const float* __restrict__ d1b,
    const float* __restrict__ d2w, const float* __restrict__ d2b,
    float* __restrict__ o_imu)
{
    __shared__ float s_d1w[2560], s_d1b[32], s_d2w[576], s_d2b[6];
    __shared__ float br[8*64], gbuf[8*640];
    int tid = threadIdx.x;
    int w = tid >> 5, l = tid & 31;
    int n0 = blockIdx.x * 8;
    for (int i = tid; i < 2560; i += 256) s_d1w[i] = d1w[i];
    for (int i = tid; i < 32;   i += 256) s_d1b[i] = d1b[i];
    for (int i = tid; i < 576;  i += 256) s_d2w[i] = d2w[i];
    for (int i = tid; i < 6;    i += 256) s_d2b[i] = d2b[i];
    for (int i = tid; i < 512;  i += 256) {
        int r = i / 64, d = i % 64;
        br[i] = g_bridge[((size_t)(n0 + r))*64 + d];
    }
    __syncthreads();

    {
        float acc[4][5];
        #pragma unroll
        for (int ii = 0; ii < 4; ii++)
            #pragma unroll
            for (int k = 0; k < 5; k++) acc[ii][k] = 0.f;
        #pragma unroll
        for (int c = 0; c < 16; c++) {
            float wr[5];
            #pragma unroll
            for (int k = 0; k < 5; k++) wr[k] = s_d1w[(c*32 + l)*5 + k];
            #pragma unroll
            for (int ii = 0; ii < 4; ii++) {
                float bv = br[w*64 + c*4 + ii];
                #pragma unroll
                for (int k = 0; k < 5; k++) acc[ii][k] += bv * wr[k];
            }
        }
        float b = s_d1b[l];
        #pragma unroll
        for (int ii = 0; ii < 4; ii++)
            #pragma unroll
            for (int k = 0; k < 5; k++)
                gbuf[w*640 + l*20 + ii*5 + k] = fmaxf(acc[ii][k] + b, 0.f);
    }
    __syncthreads();

    if (l < 24) {
        int co = l >> 2, q = l & 3;
        int ll0 = q * 5;
        float acc[5];
        float b = s_d2b[co];
        #pragma unroll
        for (int j = 0; j < 5; j++) acc[j] = b;
        #pragma unroll
        for (int ci = 0; ci < 32; ci++) {
            const float* wv = &s_d2w[(co*32 + ci)*3];
            float w0 = wv[0], w1 = wv[1], w2 = wv[2];
            const float* xr = &gbuf[w*640 + ci*20 + ll0];
            float xv[7];
            xv[0] = (ll0 == 0) ? 0.f : xr[-1];
            #pragma unroll
            for (int j = 1; j < 6; j++) xv[j] = xr[j-1];
            xv[6] = (ll0 == 15) ? 0.f : xr[5];
            #pragma unroll
            for (int j = 0; j < 5; j++) {
                acc[j] += w0*xv[j];
                acc[j] += w1*xv[j+1];
                acc[j] += w2*xv[j+2];
            }
        }
        #pragma unroll
        for (int j = 0; j < 5; j++)
            o_imu[((size_t)(n0 + w))*120 + co*20 + ll0 + j] = acc[j];
    }
}

// ================================= launch ====================================
extern "C" void kernel_launch(void* const* d_in, const int* in_sizes, int n_in,
                              void* d_out, int out_size)
{
    const float* x        = (const float*)d_in[0];
    const float* imu_mask = (const float*)d_in[1];
    const float* c1w = (const float*)d_in[3];
    const float* c1b = (const float*)d_in[4];
    const float* c2w = (const float*)d_in[5];
    const float* c2b = (const float*)d_in[6];
    const float* c3w = (const float*)d_in[7];
    const float* c3b = (const float*)d_in[8];
    const float* brw = (const float*)d_in[9];
    const float* brb = (const float*)d_in[10];
    const float* f1w = (const float*)d_in[11];
    const float* f1b = (const float*)d_in[12];
    const float* f2w = (const float*)d_in[13];
    const float* f2b = (const float*)d_in[14];
    const float* d1w = (const float*)d_in[15];
    const float* d1b = (const float*)d_in[16];
    const float* d2w = (const float*)d_in[17];
    const float* d2b = (const float*)d_in[18];
    const float* ae1w = (const float*)d_in[19];
    const float* ae1b = (const float*)d_in[20];
    const float* ae2w = (const float*)d_in[21];
    const float* ae2b = (const float*)d_in[22];
    const float* ae3w = (const float*)d_in[23];
    const float* ae3b = (const float*)d_in[24];
    const float* ad1w = (const float*)d_in[25];
    const float* ad1b = (const float*)d_in[26];
    const float* ad2w = (const float*)d_in[27];
    const float* ad2b = (const float*)d_in[28];
    (void)in_sizes; (void)n_in;

    float* out = (float*)d_out;
    long long A = ((long long)out_size - 6176768LL) / 23040LL;
    if (A < 1) A = 1;
    if (A > AMAX) A = AMAX;

    float* o_imu   = out;
    float* o_ag    = o_imu   + 1966080;
    float* o_mask  = o_ag    + (size_t)A*7680;
    float* o_atoms = o_mask  + (size_t)A*7680;
    float* o_bresh = o_atoms + (size_t)A*7680;
    float* o_fin   = o_bresh + 1048576;
    float* o_fo    = o_fin   + 1048576;
    float* o_fm    = o_fo    + 1048576;
    float* o_loss  = o_fm    + 1048576;

    static cudaStream_t s2 = 0;
    static cudaEvent_t ev_start = 0, ev_prep = 0, ev_enc = 0, ev_dec = 0;
    if (!s2) {
        cudaStreamCreateWithFlags(&s2, cudaStreamNonBlocking);
        cudaEventCreateWithFlags(&ev_start, cudaEventDisableTiming);
        cudaEventCreateWithFlags(&ev_prep,  cudaEventDisableTiming);
        cudaEventCreateWithFlags(&ev_enc,   cudaEventDisableTiming);
        cudaEventCreateWithFlags(&ev_dec,   cudaEventDisableTiming);
    }

    cudaEventRecord(ev_start, 0);
    cudaStreamWaitEvent(s2, ev_start, 0);

    k_prepB<<<960, 256, 0, s2>>>(ad2w);
    cudaEventRecord(ev_prep, s2);

    k_encoder<<<NROWS/8, 256>>>(x, c1w, c1b, c2w, c2b, c3w, c3b, brw, brb, o_bresh, o_fin);
    cudaEventRecord(ev_enc, 0);

    k_forecast<<<NROWS/16, 256>>>(f1w, f1b, f2w, f2b, imu_mask, o_fo, o_fm, o_loss);
    k_selectseg<<<1, 1024>>>();

    cudaStreamWaitEvent(s2, ev_enc, 0);
    k_decoder<<<NROWS/8, 256, 0, s2>>>(d1w, d1b, d2w, d2b, o_imu);
    cudaEventRecord(ev_dec, s2);

    k_atomenc<<<(unsigned)A, 256>>>(x, (float4*)o_mask, (float4*)o_atoms,
                                    ae1w, ae1b, ae2w, ae2b, ae3w, ae3b, ad1w, ad1b);

    cudaStreamWaitEvent(0, ev_prep, 0);
    dim3 gg(7680/128, (unsigned)((A + 127) / 128));
    k_gemm_atomgen<<<gg, 256>>>(ad2b, o_ag, (int)A);

    cudaStreamWaitEvent(0, ev_dec, 0);
}

// round 16
// speedup vs baseline: 1.0036x; 1.0036x over previous
#include <cuda_runtime.h>
#include <cuda_bf16.h>
#include <cuda_fp16.h>
#include <stdint.h>
#include <math.h>

#define BS   128
#define SEQ  128
#define CCH  6
#define LL   20
#define NROWS (BS*SEQ)      // 16384
#define DD   64
#define HH   256
#define MAL  10
#define WTOT 1280           // MAL*SEQ
#define KSEL 3276           // int(16384*0.2)
#define AMAX 18432

// ---------------- scratch (device globals; no runtime alloc allowed) ----------
__device__ float    g_bridge[NROWS*DD];          // 4 MB
__device__ float    g_loss[NROWS];               // natural order [b][t]
__device__ unsigned g_scores[NROWS];             // float bits
__device__ int      g_desc[AMAX*3];              // (b, start, end) per atom
__device__ int      g_total;
__device__ unsigned g_hd16[(size_t)AMAX*128];    // hd packed fp16x2
__device__ unsigned g_B16[128*7680];             // ad2w packed fp16x2, [kp][n]

// --------- fp16 pack helper ---------
__device__ __forceinline__ unsigned pk16(float v0, float v1)
{
    __half h0 = __float2half(v0);
    __half h1 = __float2half(v1);
    return (unsigned)__half_as_ushort(h0) | ((unsigned)__half_as_ushort(h1) << 16);
}
__device__ __forceinline__ void mma16816h(float* c, const unsigned* a, unsigned b0, unsigned b1)
{
    asm volatile(
        "mma.sync.aligned.m16n8k16.row.col.f32.f16.f16.f32 "
        "{%0,%1,%2,%3}, {%4,%5,%6,%7}, {%8,%9}, {%0,%1,%2,%3};\n"
        : "+f"(c[0]), "+f"(c[1]), "+f"(c[2]), "+f"(c[3])
        : "r"(a[0]), "r"(a[1]), "r"(a[2]), "r"(a[3]), "r"(b0), "r"(b1));
}

// =========================== K1: CNN encoder + bridge ========================
__global__ __launch_bounds__(256) void k_encoder(
    const float* __restrict__ x,
    const float* __restrict__ c1w, const float* __restrict__ c1b,
    const float* __restrict__ c2w, const float* __restrict__ c2b,
    const float* __restrict__ c3w, const float* __restrict__ c3b,
    const float* __restrict__ brw, const float* __restrict__ brb,
    float* __restrict__ o_bresh, float* __restrict__ o_fin)
{
    __shared__ float s_c1w[288], s_c1b[16], s_c2w[1536], s_c2b[32];
    __shared__ float s_c3w[3072], s_c3b[32], s_brb[64];
    __shared__ float bufA[8][320], bufB[8][320];
    int tid = threadIdx.x;
    for (int i = tid; i < 288;  i += 256) s_c1w[i] = c1w[i];
    for (int i = tid; i < 16;   i += 256) s_c1b[i] = c1b[i];
    for (int i = tid; i < 1536; i += 256) s_c2w[i] = c2w[i];
    for (int i = tid; i < 32;   i += 256) s_c2b[i] = c2b[i];
    for (int i = tid; i < 3072; i += 256) s_c3w[i] = c3w[i];
    for (int i = tid; i < 32;   i += 256) s_c3b[i] = c3b[i];
    for (int i = tid; i < 64;   i += 256) s_brb[i] = brb[i];
    __syncthreads();

    int w = tid >> 5, l = tid & 31;
    int n = blockIdx.x * 8 + w;
    float* A_ = bufA[w];
    float* B_ = bufB[w];

    for (int i = l; i < 120; i += 32) A_[i] = x[(size_t)n*120 + i];
    __syncwarp();

    {
        int oc = l >> 1, half = l & 1;
        int base0 = half * 10;
        float acc[10];
        float b = s_c1b[oc];
        #pragma unroll
        for (int j = 0; j < 10; j++) acc[j] = b;
        #pragma unroll
        for (int ic = 0; ic < 6; ic++) {
            const float* wv = &s_c1w[(oc*6 + ic)*3];
            float w0 = wv[0], w1 = wv[1], w2 = wv[2];
            const float* xr = &A_[ic*20 + base0];
            float xv[12];
            xv[0] = (half == 0) ? 0.f : xr[-1];
            #pragma unroll
            for (int j = 1; j < 11; j++) xv[j] = xr[j-1];
            xv[11] = (half == 1) ? 0.f : xr[10];
            #pragma unroll
            for (int j = 0; j < 10; j++) {
                acc[j] += w0*xv[j];
                acc[j] += w1*xv[j+1];
                acc[j] += w2*xv[j+2];
            }
        }
        #pragma unroll
        for (int j = 0; j < 5; j++)
            B_[oc*10 + half*5 + j] = fmaxf(fmaxf(acc[2*j], acc[2*j+1]), 0.f);
    }
    __syncwarp();

    {
        float acc[10];
        float b = s_c2b[l];
        #pragma unroll
        for (int j = 0; j < 10; j++) acc[j] = b;
        #pragma unroll
        for (int ic = 0; ic < 16; ic++) {
            const float* wv = &s_c2w[(l*16 + ic)*3];
            float w0 = wv[0], w1 = wv[1], w2 = wv[2];
            const float* xr = &B_[ic*10];
            float xv[12];
            xv[0] = 0.f;
            #pragma unroll
            for (int j = 1; j < 11; j++) xv[j] = xr[j-1];
            xv[11] = 0.f;
            #pragma unroll
            for (int j = 0; j < 10; j++) {
                acc[j] += w0*xv[j];
                acc[j] += w1*xv[j+1];
                acc[j] += w2*xv[j+2];
            }
        }
        __syncwarp();
        #pragma unroll
        for (int j = 0; j < 5; j++)
            A_[l*5 + j] = fmaxf(fmaxf(acc[2*j], acc[2*j+1]), 0.f);
    }
    __syncwarp();

    {
        float acc[5];
        float b = s_c3b[l];
        #pragma unroll
        for (int j = 0; j < 5; j++) acc[j] = b;
        #pragma unroll
        for (int ic = 0; ic < 32; ic++) {
            const float* wv = &s_c3w[(l*32 + ic)*3];
            float w0 = wv[0], w1 = wv[1], w2 = wv[2];
            const float* xr = &A_[ic*5];
            float xv[7];
            xv[0] = 0.f;
            #pragma unroll
            for (int j = 1; j < 6; j++) xv[j] = xr[j-1];
            xv[6] = 0.f;
            #pragma unroll
            for (int j = 0; j < 5; j++) {
                acc[j] += w0*xv[j];
                acc[j] += w1*xv[j+1];
                acc[j] += w2*xv[j+2];
            }
        }
        __syncwarp();
        B_[l*2 + 0] = fmaxf(fmaxf(acc[0], acc[1]), 0.f);
        B_[l*2 + 1] = fmaxf(fmaxf(acc[2], acc[3]), 0.f);
    }
    __syncwarp();

    #pragma unroll
    for (int cc = 0; cc < 2; cc++) {
        int c = l + cc*32;
        float v = s_brb[c];
        #pragma unroll 8
        for (int i2 = 0; i2 < 64; i2++) v += B_[i2] * __ldg(&brw[i2*64 + c]);
        v = 1.f / (1.f + expf(-v));
        g_bridge[(size_t)n*64 + c] = v;
        o_bresh [(size_t)n*64 + c] = v;
        o_fin   [(size_t)n*64 + c] = v;
    }
}

// ============================ K2: forecast MLP + loss ========================
__global__ __launch_bounds__(256) void k_forecast(
    const float* __restrict__ f1w, const float* __restrict__ f1b,
    const float* __restrict__ f2w, const float* __restrict__ f2b,
    const float* __restrict__ imu_mask,
    float* __restrict__ o_fo, float* __restrict__ o_fm, float* __restrict__ o_loss)
{
    __shared__ __align__(16) float shft[16*64];
    __shared__ __align__(16) float feat[16*256];
    __shared__ float fo[16*64];
    __shared__ float rmask[16];
    int tid = threadIdx.x;
    int n0 = blockIdx.x * 16;

    for (int i = tid; i < 256; i += 256) {
        int r = i >> 4, c4 = i & 15;
        int n = n0 + r, t = n & 127;
        float4 v = make_float4(0.f, 0.f, 0.f, 0.f);
        if (t != 0) v = *(const float4*)&g_bridge[((size_t)n - 1)*64 + c4*4];
        *(float4*)&shft[r*64 + c4*4] = v;
    }
    if (tid < 16) {
        int n = n0 + tid, t = n & 127;
        rmask[tid] = (t == 0) ? 0.f : imu_mask[(size_t)n*120];
    }
    __syncthreads();

    {
        float acc[16];
        float b = f1b[tid];
        #pragma unroll
        for (int r = 0; r < 16; r++) acc[r] = b;
        for (int c4 = 0; c4 < 16; c4++) {
            float w0 = f1w[(c4*4    )*256 + tid];
            float w1 = f1w[(c4*4 + 1)*256 + tid];
            float w2 = f1w[(c4*4 + 2)*256 + tid];
            float w3 = f1w[(c4*4 + 3)*256 + tid];
            #pragma unroll
            for (int r = 0; r < 16; r++) {
                float4 s = *(const float4*)&shft[r*64 + c4*4];
                acc[r] += s.x * w0;
                acc[r] += s.y * w1;
                acc[r] += s.z * w2;
                acc[r] += s.w * w3;
            }
        }
        #pragma unroll
        for (int r = 0; r < 16; r++) feat[r*256 + tid] = fmaxf(acc[r], 0.f);
    }
    __syncthreads();

    {
        int col = tid & 63, rg = tid >> 6;
        float acc[4];
        float b = f2b[col];
        #pragma unroll
        for (int u = 0; u < 4; u++) acc[u] = b;
        for (int i4 = 0; i4 < 64; i4++) {
            float w0 = f2w[(i4*4    )*64 + col];
            float w1 = f2w[(i4*4 + 1)*64 + col];
            float w2 = f2w[(i4*4 + 2)*64 + col];
            float w3 = f2w[(i4*4 + 3)*64 + col];
            #pragma unroll
            for (int u = 0; u < 4; u++) {
                float4 fv = *(const float4*)&feat[(rg*4+u)*256 + i4*4];
                acc[u] += fv.x * w0;
                acc[u] += fv.y * w1;
                acc[u] += fv.z * w2;
                acc[u] += fv.w * w3;
            }
        }
        #pragma unroll
        for (int u = 0; u < 4; u++) {
            int r = rg*4 + u;
            fo[r*64 + col] = acc[u];
            o_fo[((size_t)(n0 + r))*64 + col] = acc[u];
            o_fm[((size_t)(n0 + r))*64 + col] = rmask[r];
        }
    }
    __syncthreads();

    if (tid < 16) {
        int n = n0 + tid;
        float m = rmask[tid];
        float s = 0.f;
        for (int d = 0; d < 64; d++) {
            float df = (fo[tid*64 + d] - g_bridge[(size_t)n*64 + d]) * m;
            s += df * df;
        }
        float loss = s / 64.f;
        o_loss[n] = loss;
        g_loss[n] = loss;
        g_scores[n] = __float_as_uint(loss * m);
    }
}

// ======= K3: fused exact k-th largest (radix select) + segment build =========
// match_any-aggregated histogram (clustered bins -> 32x fewer smem atomics).
__global__ __launch_bounds__(1024) void k_selectseg()
{
    __shared__ unsigned hist[256];
    __shared__ unsigned wtot[8];
    __shared__ unsigned sprefix;
    __shared__ int srem;
    __shared__ unsigned flagw[128][4];
    __shared__ int wpre[4];
    int tid = threadIdx.x;
    int w8 = tid >> 5, l = tid & 31;

    unsigned v[16];
    float lv[16];
    #pragma unroll
    for (int j = 0; j < 16; j++) {
        v[j]  = g_scores[tid + j*1024];
        lv[j] = g_loss[tid + j*1024];
    }

    if (tid == 0) { sprefix = 0u; srem = KSEL; }
    __syncthreads();
    for (int pass = 0; pass < 4; pass++) {
        int shift = 24 - pass * 8;
        if (tid < 256) hist[tid] = 0;
        __syncthreads();
        unsigned pref = sprefix;
        int rem = srem;
        unsigned mask = (pass == 0) ? 0u : (0xFFFFFFFFu << (shift + 8));
        #pragma unroll
        for (int j = 0; j < 16; j++) {
            bool active = (v[j] & mask) == pref;
            unsigned bin = (v[j] >> shift) & 255u;
            unsigned key = active ? bin : 0xFFFFFFFFu;
            unsigned grp = __match_any_sync(0xFFFFFFFFu, key);
            int leader = __ffs(grp) - 1;
            if (active && l == leader)
                atomicAdd(&hist[bin], (unsigned)__popc(grp));
        }
        __syncthreads();
        // suffix scan via warp shuffles (warps 0..7 own 32 bins each)
        unsigned hval = 0, sval = 0;
        if (tid < 256) hval = hist[tid];
        sval = hval;
        #pragma unroll
        for (int d = 1; d < 32; d <<= 1) {
            unsigned o = __shfl_down_sync(0xFFFFFFFFu, sval, d);
            if (l + d < 32) sval += o;
        }
        if (tid < 256 && l == 0) wtot[w8] = sval;
        __syncthreads();
        if (tid < 256) {
            unsigned add = 0;
            #pragma unroll
            for (int ww = 1; ww < 8; ww++)
                if (w8 + ww < 8) add += wtot[w8 + ww];
            unsigned sfxv = sval + add;              // sum of bins >= tid
            unsigned above = sfxv - hval;            // sum of bins >  tid
            if (sfxv >= (unsigned)rem && above < (unsigned)rem) {
                sprefix = pref | ((unsigned)tid << shift);
                srem = rem - (int)above;
            }
        }
        __syncthreads();
    }
    float cutoff = __uint_as_float(sprefix);

    #pragma unroll
    for (int k = 0; k < 16; k++) {
        int i = tid + k*1024;
        bool f = lv[k] > cutoff;
        unsigned bal = __ballot_sync(0xFFFFFFFFu, f);
        if ((tid & 31) == 0) flagw[i >> 7][(i & 127) >> 5] = bal;
    }
    __syncthreads();

    int segs[160];
    int ns = 0;
    if (tid < 128) {
        int prev = -1;
        #pragma unroll
        for (int wi = 0; wi < 4; wi++) {
            unsigned wv = flagw[tid][wi];
            while (wv) {
                int t = wi*32 + __ffs(wv) - 1;
                wv &= wv - 1;
                if (prev >= 0) {
                    if (t - prev > MAL) {
                        segs[ns++] = prev;
                        int cur = prev;
                        while (cur < t) { cur += MAL; if (cur >= t) break; segs[ns++] = cur; }
                    } else {
                        segs[ns++] = prev;
                    }
                }
                prev = t;
            }
        }
        if (prev >= 0) segs[ns++] = prev;
    }
    int pval = ns;
    if (tid < 128) {
        #pragma unroll
        for (int d = 1; d < 32; d <<= 1) {
            int o = __shfl_up_sync(0xFFFFFFFFu, pval, d);
            if (l >= d) pval += o;
        }
        if (l == 31) wpre[w8] = pval;
    }
    __syncthreads();
    if (tid < 128) {
        int add = 0;
        #pragma unroll
        for (int ww = 0; ww < 4; ww++)
            if (ww < w8) add += wpre[ww];
        int inc = pval + add;
        int off = inc - ns;
        if (tid == 127) {
            int tot = inc;
            g_total = tot;
            if (tot == 0) { g_desc[0] = -1; g_desc[1] = 0; g_desc[2] = 0; }
        }
        int last = 0;
        for (int i = 0; i < ns; i++) {
            int e = segs[i];
            g_desc[(off + i)*3 + 0] = tid;
            g_desc[(off + i)*3 + 1] = last;
            g_desc[(off + i)*3 + 2] = e;
            last = e;
        }
    }
}

// ===== K5: fused atom fill (mask/atoms) + atom encoder -> hd fp16 packed =====
__global__ __launch_bounds__(256) void k_atomenc(
    const float* __restrict__ x,
    float4* __restrict__ o_mask, float4* __restrict__ o_atoms,
    const float* __restrict__ ae1w, const float* __restrict__ ae1b,
    const float* __restrict__ ae2w, const float* __restrict__ ae2b,
    const float* __restrict__ ae3w, const float* __restrict__ ae3b,
    const float* __restrict__ ad1w, const float* __restrict__ ad1b)
{
    __shared__ float saf[640], sw1[6144];
    __shared__ float spart[8][320];
    __shared__ float sh1[320], sp1[160], sh2[80], semb[32];
    int g = blockIdx.x, tid = threadIdx.x;
    int w = tid >> 5, l = tid & 31;
    int b = g_desc[g*3 + 0], s = g_desc[g*3 + 1], e = g_desc[g*3 + 2];

    for (int i = tid; i < 6144; i += 256) sw1[i] = ae1w[i];
    for (int i = tid; i < 640; i += 256) {
        int d = i / 10, t = i % 10;
        int row = e - 10 + t;
        saf[i] = (b >= 0 && row >= s) ? g_bridge[((size_t)b*SEQ + row)*64 + d] : 0.f;
    }

    {
        const float4 z4 = make_float4(0.f, 0.f, 0.f, 0.f);
        const float4 o4 = make_float4(1.f, 1.f, 1.f, 1.f);
        int wdt = e - s, ap = WTOT - wdt * LL;
        for (int i = tid; i < 1920; i += 256) {
            float4 mv = z4, val = z4;
            if (b >= 0) {
                int c = i / 320;
                int r4 = i - c*320;
                int colg = r4*4 - ap;
                if (colg >= 0) {
                    mv = o4;
                    int trow = colg / 20;
                    int ll = colg - trow*20;
                    val = *(const float4*)&x[(((size_t)b*SEQ + s + trow)*CCH + c)*LL + ll];
                }
            }
            o_mask [(size_t)g*1920 + i] = mv;
            o_atoms[(size_t)g*1920 + i] = val;
        }
    }
    __syncthreads();

    {
        float acc[10];
        #pragma unroll
        for (int j = 0; j < 10; j++) acc[j] = 0.f;
        #pragma unroll
        for (int ick = 0; ick < 8; ick++) {
            int ic = w*8 + ick;
            const float* wv = &sw1[(l*64 + ic)*3];
            float w0 = wv[0], w1 = wv[1], w2 = wv[2];
            float xv[12];
            xv[0] = 0.f;
            #pragma unroll
            for (int j = 1; j < 11; j++) xv[j] = saf[ic*10 + j - 1];
            xv[11] = 0.f;
            #pragma unroll
            for (int j = 0; j < 10; j++) {
                acc[j] += w0*xv[j];
                acc[j] += w1*xv[j+1];
                acc[j] += w2*xv[j+2];
            }
        }
        #pragma unroll
        for (int j = 0; j < 10; j++) spart[w][l*10 + j] = acc[j];
    }
    __syncthreads();
    for (int i = tid; i < 320; i += 256) {
        float sv = ae1b[i/10];
        #pragma unroll
        for (int ww = 0; ww < 8; ww++) sv += spart[ww][i];
        sh1[i] = fmaxf(sv, 0.f);
    }
    __syncthreads();
    for (int i = tid; i < 160; i += 256) { int oc=i/5, p=i%5; sp1[i] = fmaxf(sh1[oc*10+2*p], sh1[oc*10+2*p+1]); }
    __syncthreads();
    for (int i = tid; i < 80; i += 256) {
        int oc = i / 5, p = i % 5;
        float v = ae2b[oc];
        #pragma unroll
        for (int ic = 0; ic < 32; ic++) {
            const float* wv = &ae2w[(oc*32+ic)*3];
            const float* xr = &sp1[ic*5];
            if (p > 0) v += wv[0]*xr[p-1];
            v += wv[1]*xr[p];
            if (p < 4) v += wv[2]*xr[p+1];
        }
        sh2[i] = fmaxf(v, 0.f);
    }
    __syncthreads();
    for (int i = tid; i < 32; i += 256) {
        float v = ae3b[i];
        for (int j = 0; j < 80; j++) v += sh2[j] * ae3w[j*32 + i];
        semb[i] = v;
    }
    __syncthreads();
    if (tid < 128) {
        int c0 = 2*tid;
        float v0 = ad1b[c0], v1 = ad1b[c0 + 1];
        #pragma unroll
        for (int j = 0; j < 32; j++) {
            float ev = semb[j];
            v0 += ev * ad1w[j*256 + c0];
            v1 += ev * ad1w[j*256 + c0 + 1];
        }
        v0 = fmaxf(v0, 0.f);
        v1 = fmaxf(v1, 0.f);
        g_hd16[(size_t)g*128 + tid] = pk16(v0, v1);
    }
}

// ============ K6p: pre-pack ad2w into fp16x2  ================================
__global__ __launch_bounds__(256) void k_prepB(const float* __restrict__ Bw)
{
    int i = blockIdx.x * 256 + threadIdx.x;
    int kp = i / 1920;
    int n0 = (i - kp*1920) * 4;
    const float4 a = *(const float4*)&Bw[(size_t)(2*kp)*7680 + n0];
    const float4 b = *(const float4*)&Bw[(size_t)(2*kp + 1)*7680 + n0];
    uint4 H;
    H.x = pk16(a.x, b.x);
    H.y = pk16(a.y, b.y);
    H.z = pk16(a.z, b.z);
    H.w = pk16(a.w, b.w);
    *(uint4*)&g_B16[(size_t)kp*7680 + n0] = H;
}

// ==== K6b: atom_gen GEMM via fp16 tensor cores (software-pipelined k-loop) ===
#define ASTR 136
__global__ __launch_bounds__(256) void k_gemm_atomgen(
    const float* __restrict__ bias, float* __restrict__ Cout, int M)
{
    __shared__ __align__(16) unsigned As[16][ASTR];
    __shared__ __align__(16) unsigned Bs[16][ASTR];
    int tid = threadIdx.x;
    int lane = tid & 31, wid = tid >> 5;
    int warp_m = wid & 3, warp_n = wid >> 2;
    int gtop = lane >> 2, tig = lane & 3;
    int row0 = blockIdx.y * 128, col0 = blockIdx.x * 128;

    float acc[2][8][4];
    #pragma unroll
    for (int r = 0; r < 2; r++)
        #pragma unroll
        for (int nt = 0; nt < 8; nt++)
            #pragma unroll
            for (int q = 0; q < 4; q++) acc[r][nt][q] = 0.f;

    unsigned aR[8];
    uint4 bR[2];

    {
        int kp2 = 0;
        #pragma unroll
        for (int it = 0; it < 8; it++) {
            int idx = tid + it*256;
            int m = idx >> 4, kp = idx & 15;
            int gr = row0 + m;
            aR[it] = (gr < M) ? g_hd16[(size_t)gr*128 + kp2 + kp] : 0u;
        }
        #pragma unroll
        for (int it = 0; it < 2; it++) {
            int e = tid + it*256;
            int kp = e >> 5, n4 = (e & 31) << 2;
            bR[it] = *(const uint4*)&g_B16[(size_t)(kp2 + kp)*7680 + col0 + n4];
        }
    }

    for (int chunk = 0; chunk < 8; chunk++) {
        #pragma unroll
        for (int it = 0; it < 8; it++) {
            int idx = tid + it*256;
            int m = idx >> 4, kp = idx & 15;
            As[kp][m] = aR[it];
        }
        #pragma unroll
        for (int it = 0; it < 2; it++) {
            int e = tid + it*256;
            int kp = e >> 5, n4 = (e & 31) << 2;
            *(uint4*)&Bs[kp][n4] = bR[it];
        }
        __syncthreads();

        if (chunk < 7) {
            int kp2 = (chunk + 1) * 16;
            #pragma unroll
            for (int it = 0; it < 8; it++) {
                int idx = tid + it*256;
                int m = idx >> 4, kp = idx & 15;
                int gr = row0 + m;
                aR[it] = (gr < M) ? g_hd16[(size_t)gr*128 + kp2 + kp] : 0u;
            }
            #pragma unroll
            for (int it = 0; it < 2; it++) {
                int e = tid + it*256;
                int kp = e >> 5, n4 = (e & 31) << 2;
                bR[it] = *(const uint4*)&g_B16[(size_t)(kp2 + kp)*7680 + col0 + n4];
            }
        }

        #pragma unroll
        for (int ks = 0; ks < 2; ks++) {
            unsigned a[2][4];
            #pragma unroll
            for (int r = 0; r < 2; r++) {
                int mrow = warp_m*32 + r*16;
                a[r][0] = As[ks*8 + tig    ][mrow + gtop];
                a[r][1] = As[ks*8 + tig    ][mrow + gtop + 8];
                a[r][2] = As[ks*8 + tig + 4][mrow + gtop];
                a[r][3] = As[ks*8 + tig + 4][mrow + gtop + 8];
            }
            #pragma unroll
            for (int nt = 0; nt < 8; nt++) {
                int ncol = warp_n*64 + nt*8 + gtop;
                unsigned b0 = Bs[ks*8 + tig    ][ncol];
                unsigned b1 = Bs[ks*8 + tig + 4][ncol];
                #pragma unroll
                for (int r = 0; r < 2; r++)
                    mma16816h(acc[r][nt], a[r], b0, b1);
            }
        }
        __syncthreads();
    }

    #pragma unroll
    for (int r = 0; r < 2; r++) {
        int gr0 = row0 + warp_m*32 + r*16 + gtop;
        #pragma unroll
        for (int nt = 0; nt < 8; nt++) {
            int gc = col0 + warp_n*64 + nt*8 + 2*tig;
            float b0 = bias[gc], b1 = bias[gc + 1];
            if (gr0 < M) {
                float2 v = make_float2(acc[r][nt][0] + b0, acc[r][nt][1] + b1);
                *(float2*)&Cout[(size_t)gr0*7680 + gc] = v;
            }
            if (gr0 + 8 < M) {
                float2 v = make_float2(acc[r][nt][2] + b0, acc[r][nt][3] + b1);
                *(float2*)&Cout[(size_t)(gr0 + 8)*7680 + gc] = v;
            }
        }
    }
}

// ============================ K7: decoder -> imu_gen =========================
__global__ __launch_bounds__(256) void k_decoder(
    const float* __restrict__ d1w, const float* __restrict__ d1b,
    const float* __restrict__ d2w, const float* __restrict__ d2b,
    float* __restrict__ o_imu)
{
    __shared__ float s_d1w[2560], s_d1b[32], s_d2w[576], s_d2b[6];
    __shared__ float br[8*64], gbuf[8*640];
    int tid = threadIdx.x;
    int w = tid >> 5, l = tid & 31;
    int n0 = blockIdx.x * 8;
    for (int i = tid; i < 2560; i += 256) s_d1w[i] = d1w[i];
    for (int i = tid; i < 32;   i += 256) s_d1b[i] = d1b[i];
    for (int i = tid; i < 576;  i += 256) s_d2w[i] = d2w[i];
    for (int i = tid; i < 6;    i += 256) s_d2b[i] = d2b[i];
    for (int i = tid; i < 512;  i += 256) {
        int r = i / 64, d = i % 64;
        br[i] = g_bridge[((size_t)(n0 + r))*64 + d];
    }
    __syncthreads();

    {
        float acc[4][5];
        #pragma unroll
        for (int ii = 0; ii < 4; ii++)
            #pragma unroll
            for (int k = 0; k < 5; k++) acc[ii][k] = 0.f;
        #pragma unroll
        for (int c = 0; c < 16; c++) {
            float wr[5];
            #pragma unroll
            for (int k = 0; k < 5; k++) wr[k] = s_d1w[(c*32 + l)*5 + k];
            #pragma unroll
            for (int ii = 0; ii < 4; ii++) {
                float bv = br[w*64 + c*4 + ii];
                #pragma unroll
                for (int k = 0; k < 5; k++) acc[ii][k] += bv * wr[k];
            }
        }
        float b = s_d1b[l];
        #pragma unroll
        for (int ii = 0; ii < 4; ii++)
            #pragma unroll
            for (int k = 0; k < 5; k++)
                gbuf[w*640 + l*20 + ii*5 + k] = fmaxf(acc[ii][k] + b, 0.f);
    }
    __syncthreads();

    if (l < 24) {
        int co = l >> 2, q = l & 3;
        int ll0 = q * 5;
        float acc[5];
        float b = s_d2b[co];
        #pragma unroll
        for (int j = 0; j < 5; j++) acc[j] = b;
        #pragma unroll
        for (int ci = 0; ci < 32; ci++) {
            const float* wv = &s_d2w[(co*32 + ci)*3];
            float w0 = wv[0], w1 = wv[1], w2 = wv[2];
            const float* xr = &gbuf[w*640 + ci*20 + ll0];
            float xv[7];
            xv[0] = (ll0 == 0) ? 0.f : xr[-1];
            #pragma unroll
            for (int j = 1; j < 6; j++) xv[j] = xr[j-1];
            xv[6] = (ll0 == 15) ? 0.f : xr[5];
            #pragma unroll
            for (int j = 0; j < 5; j++) {
                acc[j] += w0*xv[j];
                acc[j] += w1*xv[j+1];
                acc[j] += w2*xv[j+2];
            }
        }
        #pragma unroll
        for (int j = 0; j < 5; j++)
            o_imu[((size_t)(n0 + w))*120 + co*20 + ll0 + j] = acc[j];
    }
}

// ================================= launch ====================================
extern "C" void kernel_launch(void* const* d_in, const int* in_sizes, int n_in,
                              void* d_out, int out_size)
{
    const float* x        = (const float*)d_in[0];
    const float* imu_mask = (const float*)d_in[1];
    const float* c1w = (const float*)d_in[3];
    const float* c1b = (const float*)d_in[4];
    const float* c2w = (const float*)d_in[5];
    const float* c2b = (const float*)d_in[6];
    const float* c3w = (const float*)d_in[7];
    const float* c3b = (const float*)d_in[8];
    const float* brw = (const float*)d_in[9];
    const float* brb = (const float*)d_in[10];
    const float* f1w = (const float*)d_in[11];
    const float* f1b = (const float*)d_in[12];
    const float* f2w = (const float*)d_in[13];
    const float* f2b = (const float*)d_in[14];
    const float* d1w = (const float*)d_in[15];
    const float* d1b = (const float*)d_in[16];
    const float* d2w = (const float*)d_in[17];
    const float* d2b = (const float*)d_in[18];
    const float* ae1w = (const float*)d_in[19];
    const float* ae1b = (const float*)d_in[20];
    const float* ae2w = (const float*)d_in[21];
    const float* ae2b = (const float*)d_in[22];
    const float* ae3w = (const float*)d_in[23];
    const float* ae3b = (const float*)d_in[24];
    const float* ad1w = (const float*)d_in[25];
    const float* ad1b = (const float*)d_in[26];
    const float* ad2w = (const float*)d_in[27];
    const float* ad2b = (const float*)d_in[28];
    (void)in_sizes; (void)n_in;

    float* out = (float*)d_out;
    long long A = ((long long)out_size - 6176768LL) / 23040LL;
    if (A < 1) A = 1;
    if (A > AMAX) A = AMAX;

    float* o_imu   = out;
    float* o_ag    = o_imu   + 1966080;
    float* o_mask  = o_ag    + (size_t)A*7680;
    float* o_atoms = o_mask  + (size_t)A*7680;
    float* o_bresh = o_atoms + (size_t)A*7680;
    float* o_fin   = o_bresh + 1048576;
    float* o_fo    = o_fin   + 1048576;
    float* o_fm    = o_fo    + 1048576;
    float* o_loss  = o_fm    + 1048576;

    static cudaStream_t s2 = 0;
    static cudaEvent_t ev_start = 0, ev_prep = 0, ev_enc = 0, ev_dec = 0;
    if (!s2) {
        cudaStreamCreateWithFlags(&s2, cudaStreamNonBlocking);
        cudaEventCreateWithFlags(&ev_start, cudaEventDisableTiming);
        cudaEventCreateWithFlags(&ev_prep,  cudaEventDisableTiming);
        cudaEventCreateWithFlags(&ev_enc,   cudaEventDisableTiming);
        cudaEventCreateWithFlags(&ev_dec,   cudaEventDisableTiming);
    }

    cudaEventRecord(ev_start, 0);
    cudaStreamWaitEvent(s2, ev_start, 0);

    k_prepB<<<960, 256, 0, s2>>>(ad2w);
    cudaEventRecord(ev_prep, s2);

    k_encoder<<<NROWS/8, 256>>>(x, c1w, c1b, c2w, c2b, c3w, c3b, brw, brb, o_bresh, o_fin);
    cudaEventRecord(ev_enc, 0);

    k_forecast<<<NROWS/16, 256>>>(f1w, f1b, f2w, f2b, imu_mask, o_fo, o_fm, o_loss);
    k_selectseg<<<1, 1024>>>();

    cudaStreamWaitEvent(s2, ev_enc, 0);
    k_decoder<<<NROWS/8, 256, 0, s2>>>(d1w, d1b, d2w, d2b, o_imu);
    cudaEventRecord(ev_dec, s2);

    k_atomenc<<<(unsigned)A, 256>>>(x, (float4*)o_mask, (float4*)o_atoms,
                                    ae1w, ae1b, ae2w, ae2b, ae3w, ae3b, ad1w, ad1b);

    cudaStreamWaitEvent(0, ev_prep, 0);
    dim3 gg(7680/128, (unsigned)((A + 127) / 128));
    k_gemm_atomgen<<<gg, 256>>>(ad2b, o_ag, (int)A);

    cudaStreamWaitEvent(0, ev_dec, 0);
}

// round 17
// speedup vs baseline: 1.0297x; 1.0260x over previous
#include <cuda_runtime.h>
#include <cuda_bf16.h>
#include <cuda_fp16.h>
#include <stdint.h>
#include <math.h>

#define BS   128
#define SEQ  128
#define CCH  6
#define LL   20
#define NROWS (BS*SEQ)      // 16384
#define DD   64
#define HH   256
#define MAL  10
#define WTOT 1280           // MAL*SEQ
#define KSEL 3276           // int(16384*0.2)
#define AMAX 18432

// ---------------- scratch (device globals; no runtime alloc allowed) ----------
__device__ float    g_bridge[NROWS*DD];          // 4 MB
__device__ float    g_loss[NROWS];               // natural order [b][t]
__device__ unsigned g_scores[NROWS];             // float bits
__device__ int      g_desc[AMAX*3];              // (b, start, end) per atom
__device__ int      g_total;
__device__ unsigned g_hd16[(size_t)AMAX*128];    // hd packed fp16x2
__device__ unsigned g_B16[128*7680];             // ad2w packed fp16x2, [kp][n]

// --------- fp16 pack helper ---------
__device__ __forceinline__ unsigned pk16(float v0, float v1)
{
    __half h0 = __float2half(v0);
    __half h1 = __float2half(v1);
    return (unsigned)__half_as_ushort(h0) | ((unsigned)__half_as_ushort(h1) << 16);
}
__device__ __forceinline__ void mma16816h(float* c, const unsigned* a, unsigned b0, unsigned b1)
{
    asm volatile(
        "mma.sync.aligned.m16n8k16.row.col.f32.f16.f16.f32 "
        "{%0,%1,%2,%3}, {%4,%5,%6,%7}, {%8,%9}, {%0,%1,%2,%3};\n"
        : "+f"(c[0]), "+f"(c[1]), "+f"(c[2]), "+f"(c[3])
        : "r"(a[0]), "r"(a[1]), "r"(a[2]), "r"(a[3]), "r"(b0), "r"(b1));
}

// =========================== K1: CNN encoder + bridge ========================
__global__ __launch_bounds__(256) void k_encoder(
    const float* __restrict__ x,
    const float* __restrict__ c1w, const float* __restrict__ c1b,
    const float* __restrict__ c2w, const float* __restrict__ c2b,
    const float* __restrict__ c3w, const float* __restrict__ c3b,
    const float* __restrict__ brw, const float* __restrict__ brb,
    float* __restrict__ o_bresh, float* __restrict__ o_fin)
{
    __shared__ float s_c1w[288], s_c1b[16], s_c2w[1536], s_c2b[32];
    __shared__ float s_c3w[3072], s_c3b[32], s_brb[64];
    __shared__ float bufA[8][320], bufB[8][320];
    int tid = threadIdx.x;
    for (int i = tid; i < 288;  i += 256) s_c1w[i] = c1w[i];
    for (int i = tid; i < 16;   i += 256) s_c1b[i] = c1b[i];
    for (int i = tid; i < 1536; i += 256) s_c2w[i] = c2w[i];
    for (int i = tid; i < 32;   i += 256) s_c2b[i] = c2b[i];
    for (int i = tid; i < 3072; i += 256) s_c3w[i] = c3w[i];
    for (int i = tid; i < 32;   i += 256) s_c3b[i] = c3b[i];
    for (int i = tid; i < 64;   i += 256) s_brb[i] = brb[i];
    __syncthreads();

    int w = tid >> 5, l = tid & 31;
    int n = blockIdx.x * 8 + w;
    float* A_ = bufA[w];
    float* B_ = bufB[w];

    for (int i = l; i < 120; i += 32) A_[i] = x[(size_t)n*120 + i];
    __syncwarp();

    {
        int oc = l >> 1, half = l & 1;
        int base0 = half * 10;
        float acc[10];
        float b = s_c1b[oc];
        #pragma unroll
        for (int j = 0; j < 10; j++) acc[j] = b;
        #pragma unroll
        for (int ic = 0; ic < 6; ic++) {
            const float* wv = &s_c1w[(oc*6 + ic)*3];
            float w0 = wv[0], w1 = wv[1], w2 = wv[2];
            const float* xr = &A_[ic*20 + base0];
            float xv[12];
            xv[0] = (half == 0) ? 0.f : xr[-1];
            #pragma unroll
            for (int j = 1; j < 11; j++) xv[j] = xr[j-1];
            xv[11] = (half == 1) ? 0.f : xr[10];
            #pragma unroll
            for (int j = 0; j < 10; j++) {
                acc[j] += w0*xv[j];
                acc[j] += w1*xv[j+1];
                acc[j] += w2*xv[j+2];
            }
        }
        #pragma unroll
        for (int j = 0; j < 5; j++)
            B_[oc*10 + half*5 + j] = fmaxf(fmaxf(acc[2*j], acc[2*j+1]), 0.f);
    }
    __syncwarp();

    {
        float acc[10];
        float b = s_c2b[l];
        #pragma unroll
        for (int j = 0; j < 10; j++) acc[j] = b;
        #pragma unroll
        for (int ic = 0; ic < 16; ic++) {
            const float* wv = &s_c2w[(l*16 + ic)*3];
            float w0 = wv[0], w1 = wv[1], w2 = wv[2];
            const float* xr = &B_[ic*10];
            float xv[12];
            xv[0] = 0.f;
            #pragma unroll
            for (int j = 1; j < 11; j++) xv[j] = xr[j-1];
            xv[11] = 0.f;
            #pragma unroll
            for (int j = 0; j < 10; j++) {
                acc[j] += w0*xv[j];
                acc[j] += w1*xv[j+1];
                acc[j] += w2*xv[j+2];
            }
        }
        __syncwarp();
        #pragma unroll
        for (int j = 0; j < 5; j++)
            A_[l*5 + j] = fmaxf(fmaxf(acc[2*j], acc[2*j+1]), 0.f);
    }
    __syncwarp();

    {
        float acc[5];
        float b = s_c3b[l];
        #pragma unroll
        for (int j = 0; j < 5; j++) acc[j] = b;
        #pragma unroll
        for (int ic = 0; ic < 32; ic++) {
            const float* wv = &s_c3w[(l*32 + ic)*3];
            float w0 = wv[0], w1 = wv[1], w2 = wv[2];
            const float* xr = &A_[ic*5];
            float xv[7];
            xv[0] = 0.f;
            #pragma unroll
            for (int j = 1; j < 6; j++) xv[j] = xr[j-1];
            xv[6] = 0.f;
            #pragma unroll
            for (int j = 0; j < 5; j++) {
                acc[j] += w0*xv[j];
                acc[j] += w1*xv[j+1];
                acc[j] += w2*xv[j+2];
            }
        }
        __syncwarp();
        B_[l*2 + 0] = fmaxf(fmaxf(acc[0], acc[1]), 0.f);
        B_[l*2 + 1] = fmaxf(fmaxf(acc[2], acc[3]), 0.f);
    }
    __syncwarp();

    #pragma unroll
    for (int cc = 0; cc < 2; cc++) {
        int c = l + cc*32;
        float v = s_brb[c];
        #pragma unroll 8
        for (int i2 = 0; i2 < 64; i2++) v += B_[i2] * __ldg(&brw[i2*64 + c]);
        v = 1.f / (1.f + expf(-v));
        g_bridge[(size_t)n*64 + c] = v;
        o_bresh [(size_t)n*64 + c] = v;
        o_fin   [(size_t)n*64 + c] = v;
    }
}

// ============================ K2: forecast MLP + loss ========================
__global__ __launch_bounds__(256) void k_forecast(
    const float* __restrict__ f1w, const float* __restrict__ f1b,
    const float* __restrict__ f2w, const float* __restrict__ f2b,
    const float* __restrict__ imu_mask,
    float* __restrict__ o_fo, float* __restrict__ o_fm, float* __restrict__ o_loss)
{
    __shared__ __align__(16) float shft[16*64];
    __shared__ __align__(16) float feat[16*256];
    __shared__ float fo[16*64];
    __shared__ float rmask[16];
    int tid = threadIdx.x;
    int n0 = blockIdx.x * 16;

    for (int i = tid; i < 256; i += 256) {
        int r = i >> 4, c4 = i & 15;
        int n = n0 + r, t = n & 127;
        float4 v = make_float4(0.f, 0.f, 0.f, 0.f);
        if (t != 0) v = *(const float4*)&g_bridge[((size_t)n - 1)*64 + c4*4];
        *(float4*)&shft[r*64 + c4*4] = v;
    }
    if (tid < 16) {
        int n = n0 + tid, t = n & 127;
        rmask[tid] = (t == 0) ? 0.f : imu_mask[(size_t)n*120];
    }
    __syncthreads();

    {
        float acc[16];
        float b = f1b[tid];
        #pragma unroll
        for (int r = 0; r < 16; r++) acc[r] = b;
        for (int c4 = 0; c4 < 16; c4++) {
            float w0 = f1w[(c4*4    )*256 + tid];
            float w1 = f1w[(c4*4 + 1)*256 + tid];
            float w2 = f1w[(c4*4 + 2)*256 + tid];
            float w3 = f1w[(c4*4 + 3)*256 + tid];
            #pragma unroll
            for (int r = 0; r < 16; r++) {
                float4 s = *(const float4*)&shft[r*64 + c4*4];
                acc[r] += s.x * w0;
                acc[r] += s.y * w1;
                acc[r] += s.z * w2;
                acc[r] += s.w * w3;
            }
        }
        #pragma unroll
        for (int r = 0; r < 16; r++) feat[r*256 + tid] = fmaxf(acc[r], 0.f);
    }
    __syncthreads();

    {
        int col = tid & 63, rg = tid >> 6;
        float acc[4];
        float b = f2b[col];
        #pragma unroll
        for (int u = 0; u < 4; u++) acc[u] = b;
        for (int i4 = 0; i4 < 64; i4++) {
            float w0 = f2w[(i4*4    )*64 + col];
            float w1 = f2w[(i4*4 + 1)*64 + col];
            float w2 = f2w[(i4*4 + 2)*64 + col];
            float w3 = f2w[(i4*4 + 3)*64 + col];
            #pragma unroll
            for (int u = 0; u < 4; u++) {
                float4 fv = *(const float4*)&feat[(rg*4+u)*256 + i4*4];
                acc[u] += fv.x * w0;
                acc[u] += fv.y * w1;
                acc[u] += fv.z * w2;
                acc[u] += fv.w * w3;
            }
        }
        #pragma unroll
        for (int u = 0; u < 4; u++) {
            int r = rg*4 + u;
            fo[r*64 + col] = acc[u];
            o_fo[((size_t)(n0 + r))*64 + col] = acc[u];
            o_fm[((size_t)(n0 + r))*64 + col] = rmask[r];
        }
    }
    __syncthreads();

    if (tid < 16) {
        int n = n0 + tid;
        float m = rmask[tid];
        float s = 0.f;
        for (int d = 0; d < 64; d++) {
            float df = (fo[tid*64 + d] - g_bridge[(size_t)n*64 + d]) * m;
            s += df * df;
        }
        float loss = s / 64.f;
        o_loss[n] = loss;
        g_loss[n] = loss;
        g_scores[n] = __float_as_uint(loss * m);
    }
}

// ======= K3: fused exact k-th largest (radix select) + segment build =========
__global__ __launch_bounds__(1024) void k_selectseg()
{
    __shared__ unsigned hist[256];
    __shared__ unsigned sfx[256];
    __shared__ unsigned sprefix;
    __shared__ int srem;
    __shared__ unsigned flagw[128][4];
    __shared__ int sc[128];
    int tid = threadIdx.x;

    unsigned v[16];
    float lv[16];
    #pragma unroll
    for (int j = 0; j < 16; j++) {
        v[j]  = g_scores[tid + j*1024];
        lv[j] = g_loss[tid + j*1024];
    }

    if (tid == 0) { sprefix = 0u; srem = KSEL; }
    __syncthreads();
    for (int pass = 0; pass < 4; pass++) {
        int shift = 24 - pass * 8;
        if (tid < 256) hist[tid] = 0;
        __syncthreads();
        unsigned pref = sprefix;
        int rem = srem;
        unsigned mask = (pass == 0) ? 0u : (0xFFFFFFFFu << (shift + 8));
        #pragma unroll
        for (int j = 0; j < 16; j++)
            if ((v[j] & mask) == pref) atomicAdd(&hist[(v[j] >> shift) & 255], 1u);
        __syncthreads();
        if (tid < 256) sfx[tid] = hist[tid];
        __syncthreads();
        #pragma unroll
        for (int d = 1; d < 256; d <<= 1) {
            unsigned add = 0;
            if (tid < 256 && tid + d < 256) add = sfx[tid + d];
            __syncthreads();
            if (tid < 256) sfx[tid] += add;
            __syncthreads();
        }
        if (tid < 256) {
            unsigned above = (tid == 255) ? 0u : sfx[tid + 1];
            if (sfx[tid] >= (unsigned)rem && above < (unsigned)rem) {
                sprefix = pref | ((unsigned)tid << shift);
                srem = rem - (int)above;
            }
        }
        __syncthreads();
    }
    float cutoff = __uint_as_float(sprefix);

    #pragma unroll
    for (int k = 0; k < 16; k++) {
        int i = tid + k*1024;
        bool f = lv[k] > cutoff;
        unsigned bal = __ballot_sync(0xFFFFFFFFu, f);
        if ((tid & 31) == 0) flagw[i >> 7][(i & 127) >> 5] = bal;
    }
    __syncthreads();

    int segs[160];
    int ns = 0;
    if (tid < 128) {
        int prev = -1;
        #pragma unroll
        for (int wi = 0; wi < 4; wi++) {
            unsigned wv = flagw[tid][wi];
            while (wv) {
                int t = wi*32 + __ffs(wv) - 1;
                wv &= wv - 1;
                if (prev >= 0) {
                    if (t - prev > MAL) {
                        segs[ns++] = prev;
                        int cur = prev;
                        while (cur < t) { cur += MAL; if (cur >= t) break; segs[ns++] = cur; }
                    } else {
                        segs[ns++] = prev;
                    }
                }
                prev = t;
            }
        }
        if (prev >= 0) segs[ns++] = prev;
        sc[tid] = ns;
    }
    __syncthreads();
    #pragma unroll
    for (int d = 1; d < 128; d <<= 1) {
        int add = 0;
        if (tid < 128 && tid >= d) add = sc[tid - d];
        __syncthreads();
        if (tid < 128) sc[tid] += add;
        __syncthreads();
    }
    if (tid < 128) {
        int off = sc[tid] - ns;
        if (tid == 127) {
            int tot = sc[127];
            g_total = tot;
            if (tot == 0) { g_desc[0] = -1; g_desc[1] = 0; g_desc[2] = 0; }
        }
        int last = 0;
        for (int i = 0; i < ns; i++) {
            int e = segs[i];
            g_desc[(off + i)*3 + 0] = tid;
            g_desc[(off + i)*3 + 1] = last;
            g_desc[(off + i)*3 + 2] = e;
            last = e;
        }
    }
}

// ===== K5: fused atom fill (mask/atoms) + atom encoder -> hd fp16 packed =====
__global__ __launch_bounds__(256) void k_atomenc(
    const float* __restrict__ x,
    float4* __restrict__ o_mask, float4* __restrict__ o_atoms,
    const float* __restrict__ ae1w, const float* __restrict__ ae1b,
    const float* __restrict__ ae2w, const float* __restrict__ ae2b,
    const float* __restrict__ ae3w, const float* __restrict__ ae3b,
    const float* __restrict__ ad1w, const float* __restrict__ ad1b)
{
    __shared__ float saf[640], sw1[6144];
    __shared__ float spart[8][320];
    __shared__ float sh1[320], sp1[160], sh2[80], semb[32];
    int g = blockIdx.x, tid = threadIdx.x;
    int w = tid >> 5, l = tid & 31;
    int b = g_desc[g*3 + 0], s = g_desc[g*3 + 1], e = g_desc[g*3 + 2];

    for (int i = tid; i < 6144; i += 256) sw1[i] = ae1w[i];
    for (int i = tid; i < 640; i += 256) {
        int d = i / 10, t = i % 10;
        int row = e - 10 + t;
        saf[i] = (b >= 0 && row >= s) ? g_bridge[((size_t)b*SEQ + row)*64 + d] : 0.f;
    }

    {
        const float4 z4 = make_float4(0.f, 0.f, 0.f, 0.f);
        const float4 o4 = make_float4(1.f, 1.f, 1.f, 1.f);
        int wdt = e - s, ap = WTOT - wdt * LL;
        for (int i = tid; i < 1920; i += 256) {
            float4 mv = z4, val = z4;
            if (b >= 0) {
                int c = i / 320;
                int r4 = i - c*320;
                int colg = r4*4 - ap;
                if (colg >= 0) {
                    mv = o4;
                    int trow = colg / 20;
                    int ll = colg - trow*20;
                    val = *(const float4*)&x[(((size_t)b*SEQ + s + trow)*CCH + c)*LL + ll];
                }
            }
            o_mask [(size_t)g*1920 + i] = mv;
            o_atoms[(size_t)g*1920 + i] = val;
        }
    }
    __syncthreads();

    {
        float acc[10];
        #pragma unroll
        for (int j = 0; j < 10; j++) acc[j] = 0.f;
        #pragma unroll
        for (int ick = 0; ick < 8; ick++) {
            int ic = w*8 + ick;
            const float* wv = &sw1[(l*64 + ic)*3];
            float w0 = wv[0], w1 = wv[1], w2 = wv[2];
            float xv[12];
            xv[0] = 0.f;
            #pragma unroll
            for (int j = 1; j < 11; j++) xv[j] = saf[ic*10 + j - 1];
            xv[11] = 0.f;
            #pragma unroll
            for (int j = 0; j < 10; j++) {
                acc[j] += w0*xv[j];
                acc[j] += w1*xv[j+1];
                acc[j] += w2*xv[j+2];
            }
        }
        #pragma unroll
        for (int j = 0; j < 10; j++) spart[w][l*10 + j] = acc[j];
    }
    __syncthreads();
    for (int i = tid; i < 320; i += 256) {
        float sv = ae1b[i/10];
        #pragma unroll
        for (int ww = 0; ww < 8; ww++) sv += spart[ww][i];
        sh1[i] = fmaxf(sv, 0.f);
    }
    __syncthreads();
    for (int i = tid; i < 160; i += 256) { int oc=i/5, p=i%5; sp1[i] = fmaxf(sh1[oc*10+2*p], sh1[oc*10+2*p+1]); }
    __syncthreads();
    for (int i = tid; i < 80; i += 256) {
        int oc = i / 5, p = i % 5;
        float v = ae2b[oc];
        #pragma unroll
        for (int ic = 0; ic < 32; ic++) {
            const float* wv = &ae2w[(oc*32+ic)*3];
            const float* xr = &sp1[ic*5];
            if (p > 0) v += wv[0]*xr[p-1];
            v += wv[1]*xr[p];
            if (p < 4) v += wv[2]*xr[p+1];
        }
        sh2[i] = fmaxf(v, 0.f);
    }
    __syncthreads();
    for (int i = tid; i < 32; i += 256) {
        float v = ae3b[i];
        for (int j = 0; j < 80; j++) v += sh2[j] * ae3w[j*32 + i];
        semb[i] = v;
    }
    __syncthreads();
    if (tid < 128) {
        int c0 = 2*tid;
        float v0 = ad1b[c0], v1 = ad1b[c0 + 1];
        #pragma unroll
        for (int j = 0; j < 32; j++) {
            float ev = semb[j];
            v0 += ev * ad1w[j*256 + c0];
            v1 += ev * ad1w[j*256 + c0 + 1];
        }
        v0 = fmaxf(v0, 0.f);
        v1 = fmaxf(v1, 0.f);
        g_hd16[(size_t)g*128 + tid] = pk16(v0, v1);
    }
}

// ============ K6p: pre-pack ad2w into fp16x2  ================================
__global__ __launch_bounds__(256) void k_prepB(const float* __restrict__ Bw)
{
    int i = blockIdx.x * 256 + threadIdx.x;
    int kp = i / 1920;
    int n0 = (i - kp*1920) * 4;
    const float4 a = *(const float4*)&Bw[(size_t)(2*kp)*7680 + n0];
    const float4 b = *(const float4*)&Bw[(size_t)(2*kp + 1)*7680 + n0];
    uint4 H;
    H.x = pk16(a.x, b.x);
    H.y = pk16(a.y, b.y);
    H.z = pk16(a.z, b.z);
    H.w = pk16(a.w, b.w);
    *(uint4*)&g_B16[(size_t)kp*7680 + n0] = H;
}

// ==== K6b: atom_gen GEMM via fp16 tensor cores (software-pipelined k-loop) ===
#define ASTR 136
__global__ __launch_bounds__(256) void k_gemm_atomgen(
    const float* __restrict__ bias, float* __restrict__ Cout, int M)
{
    __shared__ __align__(16) unsigned As[16][ASTR];
    __shared__ __align__(16) unsigned Bs[16][ASTR];
    int tid = threadIdx.x;
    int lane = tid & 31, wid = tid >> 5;
    int warp_m = wid & 3, warp_n = wid >> 2;
    int gtop = lane >> 2, tig = lane & 3;
    int row0 = blockIdx.y * 128, col0 = blockIdx.x * 128;

    float acc[2][8][4];
    #pragma unroll
    for (int r = 0; r < 2; r++)
        #pragma unroll
        for (int nt = 0; nt < 8; nt++)
            #pragma unroll
            for (int q = 0; q < 4; q++) acc[r][nt][q] = 0.f;

    unsigned aR[8];
    uint4 bR[2];

    {
        int kp2 = 0;
        #pragma unroll
        for (int it = 0; it < 8; it++) {
            int idx = tid + it*256;
            int m = idx >> 4, kp = idx & 15;
            int gr = row0 + m;
            aR[it] = (gr < M) ? g_hd16[(size_t)gr*128 + kp2 + kp] : 0u;
        }
        #pragma unroll
        for (int it = 0; it < 2; it++) {
            int e = tid + it*256;
            int kp = e >> 5, n4 = (e & 31) << 2;
            bR[it] = *(const uint4*)&g_B16[(size_t)(kp2 + kp)*7680 + col0 + n4];
        }
    }

    for (int chunk = 0; chunk < 8; chunk++) {
        #pragma unroll
        for (int it = 0; it < 8; it++) {
            int idx = tid + it*256;
            int m = idx >> 4, kp = idx & 15;
            As[kp][m] = aR[it];
        }
        #pragma unroll
        for (int it = 0; it < 2; it++) {
            int e = tid + it*256;
            int kp = e >> 5, n4 = (e & 31) << 2;
            *(uint4*)&Bs[kp][n4] = bR[it];
        }
        __syncthreads();

        if (chunk < 7) {
            int kp2 = (chunk + 1) * 16;
            #pragma unroll
            for (int it = 0; it < 8; it++) {
                int idx = tid + it*256;
                int m = idx >> 4, kp = idx & 15;
                int gr = row0 + m;
                aR[it] = (gr < M) ? g_hd16[(size_t)gr*128 + kp2 + kp] : 0u;
            }
            #pragma unroll
            for (int it = 0; it < 2; it++) {
                int e = tid + it*256;
                int kp = e >> 5, n4 = (e & 31) << 2;
                bR[it] = *(const uint4*)&g_B16[(size_t)(kp2 + kp)*7680 + col0 + n4];
            }
        }

        #pragma unroll
        for (int ks = 0; ks < 2; ks++) {
            unsigned a[2][4];
            #pragma unroll
            for (int r = 0; r < 2; r++) {
                int mrow = warp_m*32 + r*16;
                a[r][0] = As[ks*8 + tig    ][mrow + gtop];
                a[r][1] = As[ks*8 + tig    ][mrow + gtop + 8];
                a[r][2] = As[ks*8 + tig + 4][mrow + gtop];
                a[r][3] = As[ks*8 + tig + 4][mrow + gtop + 8];
            }
            #pragma unroll
            for (int nt = 0; nt < 8; nt++) {
                int ncol = warp_n*64 + nt*8 + gtop;
                unsigned b0 = Bs[ks*8 + tig    ][ncol];
                unsigned b1 = Bs[ks*8 + tig + 4][ncol];
                #pragma unroll
                for (int r = 0; r < 2; r++)
                    mma16816h(acc[r][nt], a[r], b0, b1);
            }
        }
        __syncthreads();
    }

    #pragma unroll
    for (int r = 0; r < 2; r++) {
        int gr0 = row0 + warp_m*32 + r*16 + gtop;
        #pragma unroll
        for (int nt = 0; nt < 8; nt++) {
            int gc = col0 + warp_n*64 + nt*8 + 2*tig;
            float b0 = bias[gc], b1 = bias[gc + 1];
            if (gr0 < M) {
                float2 v = make_float2(acc[r][nt][0] + b0, acc[r][nt][1] + b1);
                *(float2*)&Cout[(size_t)gr0*7680 + gc] = v;
            }
            if (gr0 + 8 < M) {
                float2 v = make_float2(acc[r][nt][2] + b0, acc[r][nt][3] + b1);
                *(float2*)&Cout[(size_t)(gr0 + 8)*7680 + gc] = v;
            }
        }
    }
}

// ============================ K7: decoder -> imu_gen =========================
__global__ __launch_bounds__(256) void k_decoder(
    const float* __restrict__ d1w, const float* __restrict__ d1b,
    const float* __restrict__ d2w, const float* __restrict__ d2b,
    float* __restrict__ o_imu)
{
    __shared__ float s_d1w[2560], s_d1b[32], s_d2w[576], s_d2b[6];
    __shared__ float br[8*64], gbuf[8*640];
    int tid = threadIdx.x;
    int w = tid >> 5, l = tid & 31;
    int n0 = blockIdx.x * 8;
    for (int i = tid; i < 2560; i += 256) s_d1w[i] = d1w[i];
    for (int i = tid; i < 32;   i += 256) s_d1b[i] = d1b[i];
    for (int i = tid; i < 576;  i += 256) s_d2w[i] = d2w[i];
    for (int i = tid; i < 6;    i += 256) s_d2b[i] = d2b[i];
    for (int i = tid; i < 512;  i += 256) {
        int r = i / 64, d = i % 64;
        br[i] = g_bridge[((size_t)(n0 + r))*64 + d];
    }
    __syncthreads();

    {
        float acc[4][5];
        #pragma unroll
        for (int ii = 0; ii < 4; ii++)
            #pragma unroll
            for (int k = 0; k < 5; k++) acc[ii][k] = 0.f;
        #pragma unroll
        for (int c = 0; c < 16; c++) {
            float wr[5];
            #pragma unroll
            for (int k = 0; k < 5; k++) wr[k] = s_d1w[(c*32 + l)*5 + k];
            #pragma unroll
            for (int ii = 0; ii < 4; ii++) {
                float bv = br[w*64 + c*4 + ii];
                #pragma unroll
                for (int k = 0; k < 5; k++) acc[ii][k] += bv * wr[k];
            }
        }
        float b = s_d1b[l];
        #pragma unroll
        for (int ii = 0; ii < 4; ii++)
            #pragma unroll
            for (int k = 0; k < 5; k++)
                gbuf[w*640 + l*20 + ii*5 + k] = fmaxf(acc[ii][k] + b, 0.f);
    }
    __syncthreads();

    if (l < 24) {
        int co = l >> 2, q = l & 3;
        int ll0 = q * 5;
        float acc[5];
        float b = s_d2b[co];
        #pragma unroll
        for (int j = 0; j < 5; j++) acc[j] = b;
        #pragma unroll
        for (int ci = 0; ci < 32; ci++) {
            const float* wv = &s_d2w[(co*32 + ci)*3];
            float w0 = wv[0], w1 = wv[1], w2 = wv[2];
            const float* xr = &gbuf[w*640 + ci*20 + ll0];
            float xv[7];
            xv[0] = (ll0 == 0) ? 0.f : xr[-1];
            #pragma unroll
            for (int j = 1; j < 6; j++) xv[j] = xr[j-1];
            xv[6] = (ll0 == 15) ? 0.f : xr[5];
            #pragma unroll
            for (int j = 0; j < 5; j++) {
                acc[j] += w0*xv[j];
                acc[j] += w1*xv[j+1];
                acc[j] += w2*xv[j+2];
            }
        }
        #pragma unroll
        for (int j = 0; j < 5; j++)
            o_imu[((size_t)(n0 + w))*120 + co*20 + ll0 + j] = acc[j];
    }
}

// ================================= launch ====================================
extern "C" void kernel_launch(void* const* d_in, const int* in_sizes, int n_in,
                              void* d_out, int out_size)
{
    const float* x        = (const float*)d_in[0];
    const float* imu_mask = (const float*)d_in[1];
    const float* c1w = (const float*)d_in[3];
    const float* c1b = (const float*)d_in[4];
    const float* c2w = (const float*)d_in[5];
    const float* c2b = (const float*)d_in[6];
    const float* c3w = (const float*)d_in[7];
    const float* c3b = (const float*)d_in[8];
    const float* brw = (const float*)d_in[9];
    const float* brb = (const float*)d_in[10];
    const float* f1w = (const float*)d_in[11];
    const float* f1b = (const float*)d_in[12];
    const float* f2w = (const float*)d_in[13];
    const float* f2b = (const float*)d_in[14];
    const float* d1w = (const float*)d_in[15];
    const float* d1b = (const float*)d_in[16];
    const float* d2w = (const float*)d_in[17];
    const float* d2b = (const float*)d_in[18];
    const float* ae1w = (const float*)d_in[19];
    const float* ae1b = (const float*)d_in[20];
    const float* ae2w = (const float*)d_in[21];
    const float* ae2b = (const float*)d_in[22];
    const float* ae3w = (const float*)d_in[23];
    const float* ae3b = (const float*)d_in[24];
    const float* ad1w = (const float*)d_in[25];
    const float* ad1b = (const float*)d_in[26];
    const float* ad2w = (const float*)d_in[27];
    const float* ad2b = (const float*)d_in[28];
    (void)in_sizes; (void)n_in;

    float* out = (float*)d_out;
    long long A = ((long long)out_size - 6176768LL) / 23040LL;
    if (A < 1) A = 1;
    if (A > AMAX) A = AMAX;

    float* o_imu   = out;
    float* o_ag    = o_imu   + 1966080;
    float* o_mask  = o_ag    + (size_t)A*7680;
    float* o_atoms = o_mask  + (size_t)A*7680;
    float* o_bresh = o_atoms + (size_t)A*7680;
    float* o_fin   = o_bresh + 1048576;
    float* o_fo    = o_fin   + 1048576;
    float* o_fm    = o_fo    + 1048576;
    float* o_loss  = o_fm    + 1048576;

    static cudaStream_t s2 = 0;
    static cudaEvent_t ev_start = 0, ev_prep = 0, ev_enc = 0, ev_dec = 0;
    if (!s2) {
        cudaStreamCreateWithFlags(&s2, cudaStreamNonBlocking);
        cudaEventCreateWithFlags(&ev_start, cudaEventDisableTiming);
        cudaEventCreateWithFlags(&ev_prep,  cudaEventDisableTiming);
        cudaEventCreateWithFlags(&ev_enc,   cudaEventDisableTiming);
        cudaEventCreateWithFlags(&ev_dec,   cudaEventDisableTiming);
    }

    cudaEventRecord(ev_start, 0);
    cudaStreamWaitEvent(s2, ev_start, 0);

    k_prepB<<<960, 256, 0, s2>>>(ad2w);
    cudaEventRecord(ev_prep, s2);

    k_encoder<<<NROWS/8, 256>>>(x, c1w, c1b, c2w, c2b, c3w, c3b, brw, brb, o_bresh, o_fin);
    cudaEventRecord(ev_enc, 0);

    k_forecast<<<NROWS/16, 256>>>(f1w, f1b, f2w, f2b, imu_mask, o_fo, o_fm, o_loss);
    k_selectseg<<<1, 1024>>>();

    cudaStreamWaitEvent(s2, ev_enc, 0);
    k_decoder<<<NROWS/8, 256, 0, s2>>>(d1w, d1b, d2w, d2b, o_imu);
    cudaEventRecord(ev_dec, s2);

    k_atomenc<<<(unsigned)A, 256>>>(x, (float4*)o_mask, (float4*)o_atoms,
                                    ae1w, ae1b, ae2w, ae2b, ae3w, ae3b, ad1w, ad1b);

    cudaStreamWaitEvent(0, ev_prep, 0);
    dim3 gg(7680/128, (unsigned)((A + 127) / 128));
    k_gemm_atomgen<<<gg, 256>>>(ad2b, o_ag, (int)A);

    cudaStreamWaitEvent(0, ev_dec, 0);
}